// round 1
// baseline (speedup 1.0000x reference)
#include <cuda_runtime.h>
#include <math.h>

#define B_DIM 64
#define C_DIM 80
#define T_DIM 16384
#define NTHREADS 512
#define NWARPS (NTHREADS / 32)

// order-preserving float -> u32 key
__device__ __forceinline__ unsigned f2k(float f) {
    unsigned u = __float_as_uint(f);
    return (u & 0x80000000u) ? ~u : (u | 0x80000000u);
}
__device__ __forceinline__ float k2f(unsigned k) {
    unsigned u = (k & 0x80000000u) ? (k & 0x7FFFFFFFu) : ~k;
    return __uint_as_float(u);
}

__global__ void __launch_bounds__(NTHREADS, 3)
statpool_kernel(const float* __restrict__ x, const int* __restrict__ lengths,
                float* __restrict__ out) {
    extern __shared__ unsigned sh[];
    unsigned* keys = sh;              // [T_DIM]
    unsigned* hist = sh + T_DIM;      // [6 * 256]

    __shared__ float red_s[NWARPS];
    __shared__ float red_s2[NWARPS];
    __shared__ unsigned s_prefix[6];
    __shared__ unsigned s_k[6];
    __shared__ int s_grp[6];
    __shared__ int s_ngrp;
    __shared__ unsigned s_gpfx[6];
    __shared__ float s_w[3];

    const int row = blockIdx.x;
    const int b = row / C_DIM;
    const int c = row % C_DIM;
    const int n = lengths[b];

    const int tid = threadIdx.x;
    const int lane = tid & 31;
    const int warp = tid >> 5;

    // ---- load row, compute sum/sumsq over valid prefix, build keys in smem ----
    const float4* x4 = (const float4*)(x + (size_t)row * T_DIM);
    float sum = 0.f, sumsq = 0.f;
    for (int i = tid; i < T_DIM / 4; i += NTHREADS) {
        float4 v = x4[i];
        int t0 = i * 4;
        float vv[4] = {v.x, v.y, v.z, v.w};
#pragma unroll
        for (int j = 0; j < 4; ++j) {
            int t = t0 + j;
            float f = vv[j];
            if (t < n) {
                sum += f;
                sumsq += f * f;
                keys[t] = f2k(f);
            } else {
                keys[t] = 0xFFFFFFFFu;  // pad: sorts above everything
            }
        }
    }

    // ---- block reduce sum / sumsq ----
#pragma unroll
    for (int o = 16; o; o >>= 1) {
        sum += __shfl_down_sync(0xFFFFFFFFu, sum, o);
        sumsq += __shfl_down_sync(0xFFFFFFFFu, sumsq, o);
    }
    if (lane == 0) { red_s[warp] = sum; red_s2[warp] = sumsq; }
    __syncthreads();

    if (tid == 0) {
        float s = 0.f, s2 = 0.f;
#pragma unroll
        for (int w = 0; w < NWARPS; ++w) { s += red_s[w]; s2 += red_s2[w]; }
        float fn = (float)n;
        float mean = s / fn;
        float var = s2 / fn - mean * mean;
        var = fmaxf(var, 1e-6f);
        float sd = sqrtf(var);
        out[b * (5 * C_DIM) + 0 * C_DIM + c] = mean;
        out[b * (5 * C_DIM) + 1 * C_DIM + c] = sd;

        // quantile target ranks
        float n1 = (float)(n - 1);
        const float qs[3] = {0.25f, 0.5f, 0.75f};
#pragma unroll
        for (int q = 0; q < 3; ++q) {
            float pos = qs[q] * n1;
            float flo = floorf(pos);
            int lo = (int)flo;
            int hi = (int)ceilf(pos);
            s_k[2 * q] = (unsigned)lo;
            s_k[2 * q + 1] = (unsigned)hi;
            s_prefix[2 * q] = 0u;
            s_prefix[2 * q + 1] = 0u;
            s_w[q] = pos - flo;
        }
    }

    // ---- 4-pass MSB radix select for 6 ranks simultaneously ----
    const unsigned pmask[4] = {0u, 0xFF000000u, 0xFFFF0000u, 0xFFFFFF00u};

#pragma unroll
    for (int pass = 0; pass < 4; ++pass) {
        const int shift = 24 - 8 * pass;
        __syncthreads();  // prefixes/k from previous pass (or init) visible

        // group targets by identical prefix (disjoint element buckets)
        if (tid == 0) {
            int ng = 0;
#pragma unroll
            for (int j = 0; j < 6; ++j) {
                int g = -1;
                for (int g2 = 0; g2 < ng; ++g2)
                    if (s_gpfx[g2] == s_prefix[j]) { g = g2; break; }
                if (g < 0) { g = ng; s_gpfx[ng++] = s_prefix[j]; }
                s_grp[j] = g;
            }
            s_ngrp = ng;
        }
        // zero histograms
        for (int i = tid; i < 6 * 256; i += NTHREADS) hist[i] = 0u;
        __syncthreads();

        const int ng = s_ngrp;
        const unsigned msk = pmask[pass];
        for (int i = tid; i < T_DIM; i += NTHREADS) {
            unsigned key = keys[i];
            for (int g = 0; g < ng; ++g) {
                if (((key ^ s_gpfx[g]) & msk) == 0u) {
                    atomicAdd(&hist[g * 256 + ((key >> shift) & 255u)], 1u);
                }
            }
        }
        __syncthreads();

        // scan: warp j resolves target j's digit
        if (warp < 6) {
            const int j = warp;
            const unsigned* h = &hist[s_grp[j] * 256];
            unsigned bins[8];
            unsigned loc = 0;
#pragma unroll
            for (int d = 0; d < 8; ++d) { bins[d] = h[lane * 8 + d]; loc += bins[d]; }
            unsigned inc = loc;
#pragma unroll
            for (int o = 1; o < 32; o <<= 1) {
                unsigned v = __shfl_up_sync(0xFFFFFFFFu, inc, o);
                if (lane >= o) inc += v;
            }
            unsigned exc = inc - loc;
            unsigned kk = s_k[j];
            if (kk >= exc && kk < inc) {
                unsigned cum = exc;
#pragma unroll
                for (int d = 0; d < 8; ++d) {
                    if (kk < cum + bins[d]) {
                        s_prefix[j] |= ((unsigned)(lane * 8 + d)) << shift;
                        s_k[j] = kk - cum;
                        break;
                    }
                    cum += bins[d];
                }
            }
        }
    }
    __syncthreads();

    // ---- quantile interpolation + writeback ----
    if (tid < 3) {
        float vlo = k2f(s_prefix[2 * tid]);
        float vhi = k2f(s_prefix[2 * tid + 1]);
        float w = s_w[tid];
        out[b * (5 * C_DIM) + (2 + tid) * C_DIM + c] = vlo + w * (vhi - vlo);
    }
}

extern "C" void kernel_launch(void* const* d_in, const int* in_sizes, int n_in,
                              void* d_out, int out_size) {
    // defensively resolve input order: x has B*C*T elements, lengths has B
    const float* x;
    const int* lengths;
    if (in_sizes[0] == B_DIM) {
        lengths = (const int*)d_in[0];
        x = (const float*)d_in[1];
    } else {
        x = (const float*)d_in[0];
        lengths = (const int*)d_in[1];
    }
    float* out = (float*)d_out;

    size_t smem = (size_t)(T_DIM + 6 * 256) * sizeof(unsigned);  // ~71.7 KB
    cudaFuncSetAttribute(statpool_kernel,
                         cudaFuncAttributeMaxDynamicSharedMemorySize, (int)smem);
    statpool_kernel<<<B_DIM * C_DIM, NTHREADS, smem>>>(x, lengths, out);
}

// round 2
// speedup vs baseline: 1.0208x; 1.0208x over previous
#include <cuda_runtime.h>
#include <math.h>

#define B_DIM 64
#define C_DIM 80
#define T_DIM 16384
#define NTHREADS 512
#define NWARPS 16
#define NBIN1 4096
#define CAP 4096
#define FULL 0xFFFFFFFFu

// order-preserving float <-> u32 key (branch-free)
__device__ __forceinline__ unsigned f2k(float f) {
    unsigned u = __float_as_uint(f);
    return u ^ ((unsigned)((int)u >> 31) | 0x80000000u);
}
__device__ __forceinline__ float k2f(unsigned k) {
    unsigned m = (k & 0x80000000u) ? 0x80000000u : 0xFFFFFFFFu;
    return __uint_as_float(k ^ m);
}

__global__ void __launch_bounds__(NTHREADS, 2)
statpool_kernel(const float* __restrict__ x, const int* __restrict__ lengths,
                float* __restrict__ out) {
    extern __shared__ unsigned sh[];
    unsigned* keys  = sh;                         // [16384]
    unsigned* hist1 = sh + T_DIM;                 // [4096]  (reused as candidate list)
    unsigned* hist2 = hist1 + NBIN1;              // [6*1024] (reused as hist3)
    unsigned char* gmask = (unsigned char*)(hist2 + 6 * 1024);  // [4096] bytes

    __shared__ float red_s[NWARPS], red_s2[NWARPS];
    __shared__ unsigned wtot[NWARPS], wbase[NWARPS];
    __shared__ unsigned s_k[6];
    __shared__ float s_w[3];
    __shared__ unsigned s_pfx12[6], s_krem[6];
    __shared__ int s_g12[6];
    __shared__ unsigned s_upfx12[6];
    __shared__ int s_ng12;
    __shared__ unsigned s_dig2[6], s_krem2[6], s_p22[6];
    __shared__ int s_g3[6], s_ng3;
    __shared__ unsigned s_upfx22[6];
    __shared__ unsigned s_keyout[6];
    __shared__ int s_cnt;

    const int row = blockIdx.x;
    const int b = row / C_DIM, c = row % C_DIM;
    const int n = lengths[b];
    const int tid = threadIdx.x, lane = tid & 31, warp = tid >> 5;

    // ---- zero hist1 + counter ----
    for (int i = tid; i < NBIN1; i += NTHREADS) hist1[i] = 0u;
    if (tid == 0) s_cnt = 0;
    __syncthreads();

    // ---- load row: sum/sumsq, keys -> smem, 12-bit hist with warp-aggregated atomics ----
    const float4* x4 = (const float4*)(x + (size_t)row * T_DIM);
    float sum = 0.f, sumsq = 0.f;
    for (int i = tid; i < T_DIM / 4; i += NTHREADS) {
        float4 v = x4[i];
        int t0 = i * 4;
        float vv[4] = {v.x, v.y, v.z, v.w};
#pragma unroll
        for (int j = 0; j < 4; ++j) {
            int t = t0 + j;
            unsigned key;
            if (t < n) {
                float f = vv[j];
                sum += f; sumsq += f * f;
                key = f2k(f);
            } else {
                key = 0xFFFFFFFFu;   // pads sort above all finite values
            }
            keys[t] = key;
            unsigned digit = key >> 20;
            unsigned peers = __match_any_sync(FULL, digit);
            if (lane == __ffs(peers) - 1)
                atomicAdd(&hist1[digit], (unsigned)__popc(peers));
        }
    }

    // ---- block reduce sums ----
#pragma unroll
    for (int o = 16; o; o >>= 1) {
        sum += __shfl_down_sync(FULL, sum, o);
        sumsq += __shfl_down_sync(FULL, sumsq, o);
    }
    if (lane == 0) { red_s[warp] = sum; red_s2[warp] = sumsq; }
    __syncthreads();

    // ---- scan hist1 (inclusive, in place): thread owns 8 consecutive bins ----
    unsigned vbin[8], loc = 0;
#pragma unroll
    for (int d = 0; d < 8; ++d) { vbin[d] = hist1[tid * 8 + d]; loc += vbin[d]; }
    unsigned inc = loc;
#pragma unroll
    for (int o = 1; o < 32; o <<= 1) {
        unsigned t = __shfl_up_sync(FULL, inc, o);
        if (lane >= o) inc += t;
    }
    if (lane == 31) wtot[warp] = inc;
    __syncthreads();

    if (warp == 0) {
        unsigned t = (lane < NWARPS) ? wtot[lane] : 0u;
        unsigned ti = t;
#pragma unroll
        for (int o = 1; o < 16; o <<= 1) {
            unsigned u = __shfl_up_sync(FULL, ti, o);
            if (lane >= o) ti += u;
        }
        if (lane < NWARPS) wbase[lane] = ti - t;
    } else if (tid == 32) {
        // mean/std + rank targets (concurrent with warp0's base scan)
        float s = 0.f, s2 = 0.f;
#pragma unroll
        for (int w = 0; w < NWARPS; ++w) { s += red_s[w]; s2 += red_s2[w]; }
        float fn = (float)n;
        float mean = s / fn;
        float var = fmaxf(s2 / fn - mean * mean, 1e-6f);
        out[b * (5 * C_DIM) + 0 * C_DIM + c] = mean;
        out[b * (5 * C_DIM) + 1 * C_DIM + c] = sqrtf(var);
        float n1 = (float)(n - 1);
        const float qs[3] = {0.25f, 0.5f, 0.75f};
#pragma unroll
        for (int q = 0; q < 3; ++q) {
            float pos = qs[q] * n1;
            float flo = floorf(pos);
            s_k[2 * q]     = (unsigned)(int)flo;
            s_k[2 * q + 1] = (unsigned)(int)ceilf(pos);
            s_w[q] = pos - flo;
        }
    }
    __syncthreads();

    // write back inclusive cumulative
    unsigned run = wbase[warp] + (inc - loc);
#pragma unroll
    for (int d = 0; d < 8; ++d) { run += vbin[d]; hist1[tid * 8 + d] = run; }
    __syncthreads();

    // ---- resolve 12-bit prefix per target (6 threads binary search);
    //      others zero gmask + hist2 concurrently ----
    if (tid < 6) {
        unsigned k = s_k[tid];
        int lo = 0, hi = NBIN1 - 1;
        while (lo < hi) {
            int mid = (lo + hi) >> 1;
            if (hist1[mid] > k) hi = mid; else lo = mid + 1;
        }
        s_pfx12[tid] = (unsigned)lo;
        s_krem[tid] = k - (lo ? hist1[lo - 1] : 0u);
    }
    {   // zero gmask (1024 words) and hist2 (6144 words)
        unsigned* gm32 = (unsigned*)gmask;
        for (int i = tid; i < 1024; i += NTHREADS) gm32[i] = 0u;
        for (int i = tid; i < 6 * 1024; i += NTHREADS) hist2[i] = 0u;
    }
    __syncthreads();

    // ---- dedup 12-bit groups, fill gmask ----
    if (tid == 0) {
        int ng = 0;
#pragma unroll
        for (int j = 0; j < 6; ++j) {
            unsigned p = s_pfx12[j];
            int g = -1;
            for (int g2 = 0; g2 < ng; ++g2) if (s_upfx12[g2] == p) { g = g2; break; }
            if (g < 0) { g = ng; s_upfx12[ng++] = p; gmask[p] = (unsigned char)(g + 1); }
            s_g12[j] = g;
        }
        s_ng12 = ng;
    }
    __syncthreads();

    // ---- compaction: append candidate keys (matching any group) to list ----
    unsigned* list = hist1;  // overlay (cumulative sums no longer needed)
    for (int i = tid; i < T_DIM; i += NTHREADS) {
        unsigned key = keys[i];
        int g = gmask[key >> 20];
        unsigned bal = __ballot_sync(FULL, g != 0);
        if (bal) {
            int leader = __ffs(bal) - 1;
            int base = 0;
            if (lane == leader) base = atomicAdd(&s_cnt, __popc(bal));
            base = __shfl_sync(FULL, base, leader);
            if (g) {
                int pos = base + __popc(bal & ((1u << lane) - 1u));
                if (pos < CAP) list[pos] = key;
            }
        }
    }
    __syncthreads();

    const int cnt = s_cnt;
    const bool ovf = cnt > CAP;                 // fallback: sweep full keys array
    const unsigned* src = ovf ? keys : list;
    const int m = ovf ? T_DIM : cnt;

    // ---- level 2: bits [19:10], per-group 1024-bin histogram over candidates ----
    for (int i = tid; i < m; i += NTHREADS) {
        unsigned key = src[i];
        int g = gmask[key >> 20];
        if (g) atomicAdd(&hist2[(g - 1) * 1024 + ((key >> 10) & 1023u)], 1u);
    }
    __syncthreads();

    // level-2 scan: warp j resolves target j
    if (warp < 6) {
        const unsigned* h = hist2 + s_g12[warp] * 1024;
        unsigned kk = s_krem[warp];
        unsigned ls = 0;
        for (int t = 0; t < 32; ++t) ls += h[lane * 32 + t];
        unsigned inc2 = ls;
#pragma unroll
        for (int o = 1; o < 32; o <<= 1) {
            unsigned u = __shfl_up_sync(FULL, inc2, o);
            if (lane >= o) inc2 += u;
        }
        unsigned exc = inc2 - ls;
        if (kk >= exc && kk < inc2) {
            unsigned cum = exc;
            for (int t = 0; t < 32; ++t) {
                unsigned cb = h[lane * 32 + t];
                if (kk < cum + cb) { s_dig2[warp] = lane * 32 + t; s_krem2[warp] = kk - cum; break; }
                cum += cb;
            }
        }
    }
    __syncthreads();

    // ---- dedup 22-bit prefixes; zero hist3 (reuse hist2 buffer) ----
    if (tid == 0) {
        int ng = 0;
#pragma unroll
        for (int j = 0; j < 6; ++j) {
            unsigned p22 = (s_pfx12[j] << 10) | s_dig2[j];
            s_p22[j] = p22;
            int g = -1;
            for (int g2 = 0; g2 < ng; ++g2) if (s_upfx22[g2] == p22) { g = g2; break; }
            if (g < 0) { g = ng; s_upfx22[ng++] = p22; }
            s_g3[j] = g;
        }
        s_ng3 = ng;
    }
    __syncthreads();
    for (int i = tid; i < 6 * 1024; i += NTHREADS) hist2[i] = 0u;
    __syncthreads();

    // ---- level 3: bits [9:0] ----
    const int ng3 = s_ng3;
    for (int i = tid; i < m; i += NTHREADS) {
        unsigned key = src[i];
        unsigned p = key >> 10;
        for (int g = 0; g < ng3; ++g) {
            if (p == s_upfx22[g]) { atomicAdd(&hist2[g * 1024 + (key & 1023u)], 1u); break; }
        }
    }
    __syncthreads();

    if (warp < 6) {
        const unsigned* h = hist2 + s_g3[warp] * 1024;
        unsigned kk = s_krem2[warp];
        unsigned ls = 0;
        for (int t = 0; t < 32; ++t) ls += h[lane * 32 + t];
        unsigned inc3 = ls;
#pragma unroll
        for (int o = 1; o < 32; o <<= 1) {
            unsigned u = __shfl_up_sync(FULL, inc3, o);
            if (lane >= o) inc3 += u;
        }
        unsigned exc = inc3 - ls;
        if (kk >= exc && kk < inc3) {
            unsigned cum = exc;
            for (int t = 0; t < 32; ++t) {
                unsigned cb = h[lane * 32 + t];
                if (kk < cum + cb) { s_keyout[warp] = (s_p22[warp] << 10) | (unsigned)(lane * 32 + t); break; }
                cum += cb;
            }
        }
    }
    __syncthreads();

    // ---- quantile interpolation + writeback ----
    if (tid < 3) {
        float vlo = k2f(s_keyout[2 * tid]);
        float vhi = k2f(s_keyout[2 * tid + 1]);
        out[b * (5 * C_DIM) + (2 + tid) * C_DIM + c] = vlo + s_w[tid] * (vhi - vlo);
    }
}

extern "C" void kernel_launch(void* const* d_in, const int* in_sizes, int n_in,
                              void* d_out, int out_size) {
    const float* x;
    const int* lengths;
    if (in_sizes[0] == B_DIM) {
        lengths = (const int*)d_in[0];
        x = (const float*)d_in[1];
    } else {
        x = (const float*)d_in[0];
        lengths = (const int*)d_in[1];
    }
    float* out = (float*)d_out;

    size_t smem = (size_t)(T_DIM + NBIN1 + 6 * 1024) * sizeof(unsigned) + 4096;
    cudaFuncSetAttribute(statpool_kernel,
                         cudaFuncAttributeMaxDynamicSharedMemorySize, (int)smem);
    statpool_kernel<<<B_DIM * C_DIM, NTHREADS, smem>>>(x, lengths, out);
}

// round 4
// speedup vs baseline: 2.4363x; 2.3867x over previous
#include <cuda_runtime.h>
#include <math.h>

#define B_DIM 64
#define C_DIM 80
#define T_DIM 16384
#define NTHREADS 512
#define NWARPS 16
#define NBIN1 4096
#define CAP 4096
#define FULL 0xFFFFFFFFu

// order-preserving float <-> u32 key (branch-free)
__device__ __forceinline__ unsigned f2k(float f) {
    unsigned u = __float_as_uint(f);
    return u ^ ((unsigned)((int)u >> 31) | 0x80000000u);
}
__device__ __forceinline__ float k2f(unsigned k) {
    unsigned m = (k & 0x80000000u) ? 0x80000000u : 0xFFFFFFFFu;
    return __uint_as_float(k ^ m);
}

__global__ void __launch_bounds__(NTHREADS, 3)
statpool_kernel(const float* __restrict__ x, const int* __restrict__ lengths,
                float* __restrict__ out) {
    extern __shared__ unsigned sh[];
    unsigned* hist1 = sh;                      // [4096]; reused as candidate list
    unsigned* hist2 = sh + NBIN1;              // [6*1024]; reused for level 3
    unsigned char* gmask = (unsigned char*)(hist2 + 6 * 1024);  // [4096]

    __shared__ float red_s[NWARPS], red_s2[NWARPS];
    __shared__ unsigned wtot[NWARPS], wbase[NWARPS];
    __shared__ unsigned s_k[6];
    __shared__ float s_w[3];
    __shared__ unsigned s_pfx12[6], s_krem[6];
    __shared__ int s_g12[6];
    __shared__ unsigned s_dig2[6], s_krem2[6], s_p22[6];
    __shared__ int s_g3[6], s_ng3;
    __shared__ unsigned s_upfx22[6];
    __shared__ unsigned s_keyout[6];
    __shared__ int s_cnt;

    const int row = blockIdx.x;
    const int b = row / C_DIM, c = row % C_DIM;
    const int n = lengths[b];
    const int tid = threadIdx.x, lane = tid & 31, warp = tid >> 5;

    for (int i = tid; i < NBIN1; i += NTHREADS) hist1[i] = 0u;
    if (tid == 0) s_cnt = 0;
    __syncthreads();

    // ---- pass 1: sum/sumsq + 12-bit histogram over VALID elements only.
    //      Pads sort above all valid keys and every target rank is < n,
    //      so they can be ignored everywhere. No warp collectives here. ----
    const float4* x4 = (const float4*)(x + (size_t)row * T_DIM);
    const int nvec = (n + 3) >> 2;
    float sum = 0.f, sumsq = 0.f;
    for (int i = tid; i < nvec; i += NTHREADS) {
        float4 v = x4[i];
        const int t0 = i << 2;
        float vv[4] = {v.x, v.y, v.z, v.w};
#pragma unroll
        for (int j = 0; j < 4; ++j) {
            if (t0 + j < n) {
                float f = vv[j];
                sum += f; sumsq += f * f;
                atomicAdd(&hist1[f2k(f) >> 20], 1u);
            }
        }
    }

    // ---- block reduce sums (uniform control flow) ----
#pragma unroll
    for (int o = 16; o; o >>= 1) {
        sum += __shfl_down_sync(FULL, sum, o);
        sumsq += __shfl_down_sync(FULL, sumsq, o);
    }
    if (lane == 0) { red_s[warp] = sum; red_s2[warp] = sumsq; }
    __syncthreads();

    // ---- scan hist1 (inclusive, in place): thread owns 8 consecutive bins ----
    unsigned vbin[8], loc = 0;
#pragma unroll
    for (int d = 0; d < 8; ++d) { vbin[d] = hist1[tid * 8 + d]; loc += vbin[d]; }
    unsigned inc = loc;
#pragma unroll
    for (int o = 1; o < 32; o <<= 1) {
        unsigned t = __shfl_up_sync(FULL, inc, o);
        if (lane >= o) inc += t;
    }
    if (lane == 31) wtot[warp] = inc;
    __syncthreads();

    if (warp == 0) {
        unsigned t = (lane < NWARPS) ? wtot[lane] : 0u;
        unsigned ti = t;
#pragma unroll
        for (int o = 1; o < 16; o <<= 1) {
            unsigned u = __shfl_up_sync(FULL, ti, o);
            if (lane >= o) ti += u;
        }
        if (lane < NWARPS) wbase[lane] = ti - t;
    } else if (tid == 32) {
        // mean/std + rank targets (concurrent with warp 0's base scan)
        float s = 0.f, s2 = 0.f;
#pragma unroll
        for (int w = 0; w < NWARPS; ++w) { s += red_s[w]; s2 += red_s2[w]; }
        float fn = (float)n;
        float mean = s / fn;
        float var = fmaxf(s2 / fn - mean * mean, 1e-6f);
        out[b * (5 * C_DIM) + 0 * C_DIM + c] = mean;
        out[b * (5 * C_DIM) + 1 * C_DIM + c] = sqrtf(var);
        float n1 = (float)(n - 1);
        const float qs[3] = {0.25f, 0.5f, 0.75f};
#pragma unroll
        for (int q = 0; q < 3; ++q) {
            float pos = qs[q] * n1;
            float flo = floorf(pos);
            s_k[2 * q]     = (unsigned)(int)flo;
            s_k[2 * q + 1] = (unsigned)(int)ceilf(pos);
            s_w[q] = pos - flo;
        }
    }
    __syncthreads();

    unsigned run = wbase[warp] + (inc - loc);
#pragma unroll
    for (int d = 0; d < 8; ++d) { run += vbin[d]; hist1[tid * 8 + d] = run; }
    __syncthreads();

    // ---- resolve 12-bit prefix per target (6 threads binary search);
    //      others zero gmask + hist2 concurrently ----
    if (tid < 6) {
        unsigned k = s_k[tid];
        int lo = 0, hi = NBIN1 - 1;
        while (lo < hi) {
            int mid = (lo + hi) >> 1;
            if (hist1[mid] > k) hi = mid; else lo = mid + 1;
        }
        s_pfx12[tid] = (unsigned)lo;
        s_krem[tid] = k - (lo ? hist1[lo - 1] : 0u);
    }
    {
        unsigned* gm32 = (unsigned*)gmask;
        for (int i = tid; i < 1024; i += NTHREADS) gm32[i] = 0u;
        for (int i = tid; i < 6 * 1024; i += NTHREADS) hist2[i] = 0u;
    }
    __syncthreads();

    // ---- dedup 12-bit groups, fill gmask ----
    if (tid == 0) {
        int ng = 0;
        unsigned upfx[6];
#pragma unroll
        for (int j = 0; j < 6; ++j) {
            unsigned p = s_pfx12[j];
            int g = -1;
            for (int g2 = 0; g2 < ng; ++g2) if (upfx[g2] == p) { g = g2; break; }
            if (g < 0) { g = ng; upfx[ng++] = p; gmask[p] = (unsigned char)(g + 1); }
            s_g12[j] = g;
        }
    }
    __syncthreads();

    // ---- compaction: re-read row (L2-hot), append candidates.
    //      UNIFORM trip count: every lane runs every iteration so the
    //      warp scan/shuffles are always fully converged. ----
    unsigned* list = hist1;  // overlay (cumsums no longer needed)
    const int iters = (nvec + NTHREADS - 1) / NTHREADS;
    for (int it = 0; it < iters; ++it) {
        const int i = tid + it * NTHREADS;
        const bool vld = i < nvec;
        float4 v = vld ? x4[i] : make_float4(0.f, 0.f, 0.f, 0.f);
        const int t0 = i << 2;
        float vv[4] = {v.x, v.y, v.z, v.w};
        unsigned kk[4]; int gg[4]; int cl = 0;
#pragma unroll
        for (int j = 0; j < 4; ++j) {
            kk[j] = f2k(vv[j]);
            gg[j] = (vld && (t0 + j < n)) ? (int)gmask[kk[j] >> 20] : 0;
            cl += (gg[j] ? 1 : 0);
        }
        int incl = cl;
#pragma unroll
        for (int o = 1; o < 32; o <<= 1) {
            int t = __shfl_up_sync(FULL, incl, o);
            if (lane >= o) incl += t;
        }
        int wsum = __shfl_sync(FULL, incl, 31);
        int base = 0;
        if (lane == 31 && wsum) base = atomicAdd(&s_cnt, wsum);
        base = __shfl_sync(FULL, base, 31);
        int pos = base + incl - cl;
#pragma unroll
        for (int j = 0; j < 4; ++j) {
            if (gg[j]) { if (pos < CAP) list[pos] = kk[j]; pos++; }
        }
    }
    __syncthreads();

    const int cnt = s_cnt;
    const bool ovf = cnt > CAP;  // adversarial-data fallback: sweep gmem again

    // ---- level 2: bits [19:10], per-group 1024-bin hist over candidates ----
    if (!ovf) {
        for (int i = tid; i < cnt; i += NTHREADS) {
            unsigned key = list[i];
            int g = gmask[key >> 20];  // >= 1 by construction
            atomicAdd(&hist2[(g - 1) * 1024 + ((key >> 10) & 1023u)], 1u);
        }
    } else {
        for (int i = tid; i < nvec; i += NTHREADS) {
            float4 v = x4[i];
            const int t0 = i << 2;
            float vv[4] = {v.x, v.y, v.z, v.w};
#pragma unroll
            for (int j = 0; j < 4; ++j) {
                if (t0 + j < n) {
                    unsigned key = f2k(vv[j]);
                    int g = gmask[key >> 20];
                    if (g) atomicAdd(&hist2[(g - 1) * 1024 + ((key >> 10) & 1023u)], 1u);
                }
            }
        }
    }
    __syncthreads();

    // level-2 scan: warp j resolves target j (full-warp uniform code)
    if (warp < 6) {
        const unsigned* h = hist2 + s_g12[warp] * 1024;
        unsigned kk = s_krem[warp];
        unsigned ls = 0;
        for (int t = 0; t < 32; ++t) ls += h[lane * 32 + t];
        unsigned inc2 = ls;
#pragma unroll
        for (int o = 1; o < 32; o <<= 1) {
            unsigned u = __shfl_up_sync(FULL, inc2, o);
            if (lane >= o) inc2 += u;
        }
        unsigned exc = inc2 - ls;
        if (kk >= exc && kk < inc2) {
            unsigned cum = exc;
            for (int t = 0; t < 32; ++t) {
                unsigned cb = h[lane * 32 + t];
                if (kk < cum + cb) { s_dig2[warp] = lane * 32 + t; s_krem2[warp] = kk - cum; break; }
                cum += cb;
            }
        }
    }
    __syncthreads();

    // ---- dedup 22-bit prefixes ----
    if (tid == 0) {
        int ng = 0;
#pragma unroll
        for (int j = 0; j < 6; ++j) {
            unsigned p22 = (s_pfx12[j] << 10) | s_dig2[j];
            s_p22[j] = p22;
            int g = -1;
            for (int g2 = 0; g2 < ng; ++g2) if (s_upfx22[g2] == p22) { g = g2; break; }
            if (g < 0) { g = ng; s_upfx22[ng++] = p22; }
            s_g3[j] = g;
        }
        s_ng3 = ng;
    }
    __syncthreads();
    for (int i = tid; i < 6 * 1024; i += NTHREADS) hist2[i] = 0u;
    __syncthreads();

    // ---- level 3: bits [9:0] ----
    const int ng3 = s_ng3;
    if (!ovf) {
        for (int i = tid; i < cnt; i += NTHREADS) {
            unsigned key = list[i];
            unsigned p = key >> 10;
            for (int g = 0; g < ng3; ++g)
                if (p == s_upfx22[g]) { atomicAdd(&hist2[g * 1024 + (key & 1023u)], 1u); break; }
        }
    } else {
        for (int i = tid; i < nvec; i += NTHREADS) {
            float4 v = x4[i];
            const int t0 = i << 2;
            float vv[4] = {v.x, v.y, v.z, v.w};
#pragma unroll
            for (int j = 0; j < 4; ++j) {
                if (t0 + j < n) {
                    unsigned key = f2k(vv[j]);
                    unsigned p = key >> 10;
                    for (int g = 0; g < ng3; ++g)
                        if (p == s_upfx22[g]) { atomicAdd(&hist2[g * 1024 + (key & 1023u)], 1u); break; }
                }
            }
        }
    }
    __syncthreads();

    if (warp < 6) {
        const unsigned* h = hist2 + s_g3[warp] * 1024;
        unsigned kk = s_krem2[warp];
        unsigned ls = 0;
        for (int t = 0; t < 32; ++t) ls += h[lane * 32 + t];
        unsigned inc3 = ls;
#pragma unroll
        for (int o = 1; o < 32; o <<= 1) {
            unsigned u = __shfl_up_sync(FULL, inc3, o);
            if (lane >= o) inc3 += u;
        }
        unsigned exc = inc3 - ls;
        if (kk >= exc && kk < inc3) {
            unsigned cum = exc;
            for (int t = 0; t < 32; ++t) {
                unsigned cb = h[lane * 32 + t];
                if (kk < cum + cb) { s_keyout[warp] = (s_p22[warp] << 10) | (unsigned)(lane * 32 + t); break; }
                cum += cb;
            }
        }
    }
    __syncthreads();

    if (tid < 3) {
        float vlo = k2f(s_keyout[2 * tid]);
        float vhi = k2f(s_keyout[2 * tid + 1]);
        out[b * (5 * C_DIM) + (2 + tid) * C_DIM + c] = vlo + s_w[tid] * (vhi - vlo);
    }
}

extern "C" void kernel_launch(void* const* d_in, const int* in_sizes, int n_in,
                              void* d_out, int out_size) {
    const float* x;
    const int* lengths;
    if (in_sizes[0] == B_DIM) {
        lengths = (const int*)d_in[0];
        x = (const float*)d_in[1];
    } else {
        x = (const float*)d_in[0];
        lengths = (const int*)d_in[1];
    }
    float* out = (float*)d_out;

    size_t smem = (size_t)(NBIN1 + 6 * 1024) * sizeof(unsigned) + 4096;  // ~44 KB
    cudaFuncSetAttribute(statpool_kernel,
                         cudaFuncAttributeMaxDynamicSharedMemorySize, (int)smem);
    statpool_kernel<<<B_DIM * C_DIM, NTHREADS, smem>>>(x, lengths, out);
}